// round 1
// baseline (speedup 1.0000x reference)
#include <cuda_runtime.h>
#include <cuda_bf16.h>
#include <math.h>

// Problem constants
#define NB   2        // batch
#define C    288
#define M    9        // heads
#define D    32       // head dim
#define H    64
#define W    64
#define P    4096     // H*W queries
#define HKV  32
#define WKV  32
#define S    1024     // HKV*WKV keys
#define FEAT 144      // C/2 pos-embed width (72 sin + 72 cos)

// ---------------- device scratch ----------------
__device__ float g_xkv[NB * C * S];        // [n][c][s]
__device__ float g_qt [NB * P * C];        // [n][p][o]
__device__ float g_kt [NB * S * C];        // [n][s][o]
__device__ float g_vt [NB * S * C];        // [n][s][o]
__device__ float g_pfx[M * W * WKV * D];   // [m][wq][v][d]
__device__ float g_pfy[M * H * HKV * D];   // [m][hq][u][d]
__device__ float g_ctx[NB * C];
__device__ float g_mix[NB * M];
__device__ float g_ao [NB * P * C];        // attn output [n][p][o]

// ---------------- kernels ----------------

// Strided gather: x_kv[n][c][s] = x[n][c][2u*64 + 2v]
__global__ void xkv_kernel(const float* __restrict__ x, float* __restrict__ xkv) {
    int idx = blockIdx.x * 256 + threadIdx.x;
    if (idx >= NB * C * S) return;
    int s = idx & (S - 1);
    int c = (idx >> 10) % C;
    int n = idx / (C * S);
    int u = s >> 5, v = s & 31;
    xkv[idx] = x[((size_t)n * C + c) * P + u * 128 + v * 2];
}

// out[n][p][o] = sum_c X[n][c][p] * Wt[o][c]
// grid (P/32, O/32, NB), block (32,8). tx indexes o (coalesced stores).
__global__ void proj_kernel(const float* __restrict__ X, const float* __restrict__ Wt,
                            float* __restrict__ out, int Pn) {
    __shared__ float Xs[32][33];   // [c_local][p_local]
    __shared__ float Ws[32][33];   // [o_local][c_local]
    int n = blockIdx.z;
    const float* Xn = X + (size_t)n * C * Pn;
    float* outn = out + (size_t)n * Pn * C;
    int p0 = blockIdx.x * 32, o0 = blockIdx.y * 32;
    int tx = threadIdx.x, ty = threadIdx.y;
    float acc[4] = {0.f, 0.f, 0.f, 0.f};
    for (int c0 = 0; c0 < C; c0 += 32) {
        #pragma unroll
        for (int i = ty; i < 32; i += 8) {
            Xs[i][tx] = Xn[(size_t)(c0 + i) * Pn + p0 + tx];
            Ws[i][tx] = Wt[(size_t)(o0 + i) * C + c0 + tx];
        }
        __syncthreads();
        #pragma unroll
        for (int kk = 0; kk < 32; kk++) {
            float wv = Ws[tx][kk];
            acc[0] += Xs[kk][ty]      * wv;
            acc[1] += Xs[kk][ty + 8]  * wv;
            acc[2] += Xs[kk][ty + 16] * wv;
            acc[3] += Xs[kk][ty + 24] * wv;
        }
        __syncthreads();
    }
    #pragma unroll
    for (int j = 0; j < 4; j++)
        outn[(size_t)(p0 + ty + 8 * j) * C + o0 + tx] = acc[j];
}

// ctx[n][o] = mean_p qt[n][p][o].   grid (C, NB), block 256
__global__ void context_kernel(const float* __restrict__ qt, float* __restrict__ ctx) {
    int o = blockIdx.x, n = blockIdx.y;
    const float* q = qt + (size_t)n * P * C + o;
    float s = 0.f;
    for (int p = threadIdx.x; p < P; p += 256) s += q[(size_t)p * C];
    __shared__ float red[256];
    red[threadIdx.x] = s;
    __syncthreads();
    for (int st = 128; st > 0; st >>= 1) {
        if (threadIdx.x < st) red[threadIdx.x] += red[threadIdx.x + st];
        __syncthreads();
    }
    if (threadIdx.x == 0) ctx[n * C + o] = red[0] * (1.0f / (float)P);
}

// mix_w[n][m] = softmax_m(ctx @ Wc^T + bc).  grid NB, block 32
__global__ void mix_kernel(const float* __restrict__ ctx, const float* __restrict__ Wc,
                           const float* __restrict__ bc, float* __restrict__ mixw) {
    int n = blockIdx.x;
    __shared__ float lg[M];
    int m = threadIdx.x;
    if (m < M) {
        float s = bc[m];
        const float* cn = ctx + n * C;
        const float* wm = Wc + m * C;
        for (int o = 0; o < C; o++) s += cn[o] * wm[o];
        lg[m] = s;
    }
    __syncthreads();
    if (m == 0) {
        float mx = lg[0];
        #pragma unroll
        for (int i = 1; i < M; i++) mx = fmaxf(mx, lg[i]);
        float e[M], sum = 0.f;
        #pragma unroll
        for (int i = 0; i < M; i++) { e[i] = expf(lg[i] - mx); sum += e[i]; }
        #pragma unroll
        for (int i = 0; i < M; i++) mixw[n * M + i] = e[i] / sum;
    }
}

// Positional features. emb_x == emb_y element-wise (same index formula), so one
// emb feeds both Wx and Wy projections.
// grid (WKV=32, W=64), block 288.  pf[m][i][j][d]
__global__ void pos_kernel(const float* __restrict__ Wx, const float* __restrict__ Wy,
                           float* __restrict__ pfx, float* __restrict__ pfy) {
    __shared__ float emb[FEAT];
    int j = blockIdx.x;   // kv index
    int i = blockIdx.y;   // q index
    int t = threadIdx.x;
    float diff = (float)i - 2.0f * (float)j;   // POS_MAG=1, Q_STRIDE=1, KV_STRIDE=2
    if (t < FEAT) {
        int l = (t < 72) ? t : (t - 72);
        float dm = powf(1000.0f, (4.0f / 288.0f) * (float)l);
        float wd = diff / dm;
        emb[t] = (t < 72) ? sinf(wd) : cosf(wd);
    }
    __syncthreads();
    float sx = 0.f, sy = 0.f;
    const float* wxr = Wx + t * FEAT;
    const float* wyr = Wy + t * FEAT;
    #pragma unroll 4
    for (int l = 0; l < FEAT; l++) {
        float e = emb[l];
        sx += e * wxr[l];
        sy += e * wyr[l];
    }
    const float inv_sqrt2 = 0.70710678118654752f;
    int m = t >> 5, dd = t & 31;
    int idx = ((m * 64 + i) * 32 + j) * 32 + dd;
    pfx[idx] = sx * inv_sqrt2;
    pfy[idx] = sy * inv_sqrt2;
}

// Fused attention: per block: 16 queries (one row segment), all 9 heads.
// energy = qk + ex[v] + ey[u]; per-head softmax; mix-weighted accumulate; attn @ V.
#define QT 16
#define ATH 512
#define SMEM_FLOATS (QT*288 + QT*1024 + QT*1024 + 128*33 + QT*32 + QT*32)

__global__ void attn_kernel(const float* __restrict__ qt, const float* __restrict__ kt,
                            const float* __restrict__ vt, const float* __restrict__ pfx,
                            const float* __restrict__ pfy, const float* __restrict__ mixw,
                            float* __restrict__ ao) {
    extern __shared__ float smp[];
    float* q_s = smp;                   // QT*288
    float* acc = q_s + QT * 288;        // QT*1024
    float* e   = acc + QT * 1024;       // QT*1024 (reused as V tile in AV phase)
    float* ks  = e + QT * 1024;         // 128*33
    float* exs = ks + 128 * 33;         // QT*32
    float* eys = exs + QT * 32;         // QT*32

    int t = threadIdx.x;
    int n = blockIdx.y;
    int p0 = blockIdx.x * QT;
    const float* qn = qt + (size_t)n * P * C;
    const float* kn = kt + (size_t)n * S * C;
    const float* vn = vt + (size_t)n * S * C;
    int hq = p0 >> 6;       // all 16 queries share the row
    int wq0 = p0 & 63;

    for (int i = t; i < QT * 288; i += ATH) q_s[i] = qn[(size_t)p0 * C + i];
    for (int i = t; i < QT * 1024; i += ATH) acc[i] = 0.f;
    __syncthreads();

    int qi_w = t >> 5, lane = t & 31;

    for (int m = 0; m < M; m++) {
        // ---- QK energy, s-chunks of 128 ----
        for (int s0 = 0; s0 < S; s0 += 128) {
            for (int i = t; i < 128 * 32; i += ATH) {
                int sl = i >> 5, dd = i & 31;
                ks[sl * 33 + dd] = kn[(size_t)(s0 + sl) * C + m * 32 + dd];
            }
            __syncthreads();
            int sub = t & 127, qg = t >> 7;
            #pragma unroll
            for (int r = 0; r < 4; r++) {
                int qi = qg * 4 + r;
                const float* qp = q_s + qi * 288 + m * 32;
                const float* kp = ks + sub * 33;
                float a = 0.f;
                #pragma unroll
                for (int dd = 0; dd < 32; dd++) a += qp[dd] * kp[dd];
                e[qi * 1024 + s0 + sub] = a;
            }
            __syncthreads();
        }
        // ---- separable positional terms: ex[qi][v], ey[qi][u] ----
        {
            const float* qp = q_s + qi_w * 288 + m * 32;
            const float* px = pfx + (((m * 64 + (wq0 + qi_w)) * 32 + lane) << 5);
            const float* py = pfy + (((m * 64 + hq) * 32 + lane) << 5);
            float sx = 0.f, sy = 0.f;
            #pragma unroll
            for (int dd = 0; dd < 32; dd++) {
                float qv = qp[dd];
                sx += qv * px[dd];
                sy += qv * py[dd];
            }
            exs[qi_w * 32 + lane] = sx;
            eys[qi_w * 32 + lane] = sy;
        }
        __syncthreads();
        for (int i = t; i < QT * 1024; i += ATH) {
            int qi = i >> 10, s = i & 1023;
            e[i] += exs[(qi << 5) + (s & 31)] + eys[(qi << 5) + (s >> 5)];
        }
        __syncthreads();
        // ---- softmax (warp per query) + mix-weighted accumulate ----
        {
            float wmix = mixw[n * M + m];
            float ev[32];
            float mx = -1e30f;
            #pragma unroll
            for (int j = 0; j < 32; j++) {
                ev[j] = e[qi_w * 1024 + lane + (j << 5)];
                mx = fmaxf(mx, ev[j]);
            }
            #pragma unroll
            for (int off = 16; off > 0; off >>= 1)
                mx = fmaxf(mx, __shfl_xor_sync(0xffffffffu, mx, off));
            float ssum = 0.f;
            #pragma unroll
            for (int j = 0; j < 32; j++) { ev[j] = __expf(ev[j] - mx); ssum += ev[j]; }
            #pragma unroll
            for (int off = 16; off > 0; off >>= 1)
                ssum += __shfl_xor_sync(0xffffffffu, ssum, off);
            float sc = wmix / ssum;
            #pragma unroll
            for (int j = 0; j < 32; j++)
                acc[qi_w * 1024 + lane + (j << 5)] += ev[j] * sc;
        }
        __syncthreads();
    }

    // ---- attn @ V ----
    float* vs = e;   // reuse: needs 32*289 = 9248 floats <= 16384
    float outr[9];
    #pragma unroll
    for (int r = 0; r < 9; r++) outr[r] = 0.f;
    for (int s0 = 0; s0 < S; s0 += 32) {
        for (int i = t; i < 32 * 288; i += ATH) {
            int sl = i / 288, o = i - sl * 288;
            vs[sl * 289 + o] = vn[(size_t)(s0 + sl) * C + o];
        }
        __syncthreads();
        #pragma unroll
        for (int r = 0; r < 9; r++) {
            int idx = t + ATH * r;
            int qi = idx / 288, o = idx - qi * 288;
            const float* ap = acc + qi * 1024 + s0;
            const float* vp = vs + o;
            float a = 0.f;
            #pragma unroll
            for (int j = 0; j < 32; j++) a += ap[j] * vp[j * 289];
            outr[r] += a;
        }
        __syncthreads();
    }
    float* aon = ao + (size_t)n * P * C;
    #pragma unroll
    for (int r = 0; r < 9; r++) {
        int idx = t + ATH * r;           // idx == qi*288 + o, contiguous
        aon[(size_t)p0 * C + idx] = outr[r];
    }
}

// out[n][c][p] = gamma*(sum_o A[n][p][o]*Wproj[c][o] + bproj[c]) + x[n][c][p]
// grid (P/32, C/32, NB), block (32,8). tx indexes p (coalesced stores).
__global__ void final_kernel(const float* __restrict__ A, const float* __restrict__ Wp,
                             const float* __restrict__ bp, const float* __restrict__ x,
                             const float* __restrict__ gamma, float* __restrict__ out) {
    __shared__ float As[32][33];   // [p_local][o_local]
    __shared__ float Ws[32][33];   // [c_local][o_local]
    int n = blockIdx.z;
    const float* An = A + (size_t)n * P * C;
    int p0 = blockIdx.x * 32, c0 = blockIdx.y * 32;
    int tx = threadIdx.x, ty = threadIdx.y;
    float acc[4] = {0.f, 0.f, 0.f, 0.f};
    for (int o0 = 0; o0 < C; o0 += 32) {
        #pragma unroll
        for (int i = ty; i < 32; i += 8) {
            As[i][tx] = An[(size_t)(p0 + i) * C + o0 + tx];
            Ws[i][tx] = Wp[(size_t)(c0 + i) * C + o0 + tx];
        }
        __syncthreads();
        #pragma unroll
        for (int kk = 0; kk < 32; kk++) {
            float av = As[tx][kk];
            acc[0] += av * Ws[ty][kk];
            acc[1] += av * Ws[ty + 8][kk];
            acc[2] += av * Ws[ty + 16][kk];
            acc[3] += av * Ws[ty + 24][kk];
        }
        __syncthreads();
    }
    float g = gamma[0];
    #pragma unroll
    for (int j = 0; j < 4; j++) {
        int c = c0 + ty + 8 * j;
        int p = p0 + tx;
        size_t oi = ((size_t)n * C + c) * P + p;
        out[oi] = g * (acc[j] + bp[c]) + x[oi];
    }
}

// ---------------- launch ----------------
extern "C" void kernel_launch(void* const* d_in, const int* in_sizes, int n_in,
                              void* d_out, int out_size) {
    const float* x     = (const float*)d_in[0];
    const float* Wq    = (const float*)d_in[1];
    const float* Wk    = (const float*)d_in[2];
    const float* Wv    = (const float*)d_in[3];
    const float* Wx    = (const float*)d_in[4];
    const float* Wy    = (const float*)d_in[5];
    const float* Wproj = (const float*)d_in[6];
    const float* bproj = (const float*)d_in[7];
    const float* Wc    = (const float*)d_in[8];
    const float* bc    = (const float*)d_in[9];
    const float* gamma = (const float*)d_in[10];
    float* out = (float*)d_out;

    float *xkv, *qt, *kt, *vt, *pfx, *pfy, *ctx, *mix, *ao;
    cudaGetSymbolAddress((void**)&xkv, g_xkv);
    cudaGetSymbolAddress((void**)&qt,  g_qt);
    cudaGetSymbolAddress((void**)&kt,  g_kt);
    cudaGetSymbolAddress((void**)&vt,  g_vt);
    cudaGetSymbolAddress((void**)&pfx, g_pfx);
    cudaGetSymbolAddress((void**)&pfy, g_pfy);
    cudaGetSymbolAddress((void**)&ctx, g_ctx);
    cudaGetSymbolAddress((void**)&mix, g_mix);
    cudaGetSymbolAddress((void**)&ao,  g_ao);

    size_t attn_smem = (size_t)SMEM_FLOATS * sizeof(float);
    cudaFuncSetAttribute(attn_kernel, cudaFuncAttributeMaxDynamicSharedMemorySize,
                         (int)attn_smem);

    // 1. gather strided KV input
    xkv_kernel<<<(NB * C * S + 255) / 256, 256>>>(x, xkv);
    // 2. projections
    proj_kernel<<<dim3(P / 32, C / 32, NB), dim3(32, 8)>>>(x,   Wq, qt, P);
    proj_kernel<<<dim3(S / 32, C / 32, NB), dim3(32, 8)>>>(xkv, Wk, kt, S);
    proj_kernel<<<dim3(S / 32, C / 32, NB), dim3(32, 8)>>>(xkv, Wv, vt, S);
    // 3. head-mix weights
    context_kernel<<<dim3(C, NB), 256>>>(qt, ctx);
    mix_kernel<<<NB, 32>>>(ctx, Wc, bc, mix);
    // 4. positional features (emb_x == emb_y, one kernel makes both)
    pos_kernel<<<dim3(WKV, W), 288>>>(Wx, Wy, pfx, pfy);
    // 5. fused attention
    attn_kernel<<<dim3(P / QT, NB), ATH, attn_smem>>>(qt, kt, vt, pfx, pfy, mix, ao);
    // 6. output projection + bias + gamma residual
    final_kernel<<<dim3(P / 32, C / 32, NB), dim3(32, 8)>>>(ao, Wproj, bproj, x, gamma, out);
}

// round 2
// speedup vs baseline: 1.6377x; 1.6377x over previous
#include <cuda_runtime.h>
#include <cuda_bf16.h>
#include <math.h>

// Problem constants
#define NB   2        // batch
#define C    288
#define M    9        // heads
#define D    32       // head dim
#define H    64
#define W    64
#define P    4096     // H*W queries
#define HKV  32
#define WKV  32
#define S    1024     // HKV*WKV keys
#define FEAT 144      // C/2 pos-embed width (72 sin + 72 cos)

// ---------------- device scratch ----------------
__device__ float g_xkv[NB * C * S];        // [n][c][s]
__device__ float g_qt [NB * P * C];        // [n][p][o]
__device__ float g_kt [NB * S * C];        // [n][s][o]
__device__ float g_vt [NB * S * C];        // [n][s][o]
__device__ float g_pfx[M * W * D * WKV];   // [m][wq][d][v]  (d-major for coalesced reads)
__device__ float g_pfy[M * H * D * HKV];   // [m][hq][d][u]
__device__ float g_ctx[NB * C];
__device__ float g_mix[NB * M];
__device__ float g_ao [NB * P * C];        // attn output [n][p][o]

// ---------------- kernels ----------------

// Strided gather: x_kv[n][c][s] = x[n][c][2u*64 + 2v]
__global__ void xkv_kernel(const float* __restrict__ x, float* __restrict__ xkv) {
    int idx = blockIdx.x * 256 + threadIdx.x;
    if (idx >= NB * C * S) return;
    int s = idx & (S - 1);
    int c = (idx >> 10) % C;
    int n = idx / (C * S);
    int u = s >> 5, v = s & 31;
    xkv[idx] = x[((size_t)n * C + c) * P + u * 128 + v * 2];
}

// out[n][p][o] = sum_c X[n][c][p] * Wt[o][c]
__global__ void proj_kernel(const float* __restrict__ X, const float* __restrict__ Wt,
                            float* __restrict__ out, int Pn) {
    __shared__ float Xs[32][33];   // [c_local][p_local]
    __shared__ float Ws[32][33];   // [o_local][c_local]
    int n = blockIdx.z;
    const float* Xn = X + (size_t)n * C * Pn;
    float* outn = out + (size_t)n * Pn * C;
    int p0 = blockIdx.x * 32, o0 = blockIdx.y * 32;
    int tx = threadIdx.x, ty = threadIdx.y;
    float acc[4] = {0.f, 0.f, 0.f, 0.f};
    for (int c0 = 0; c0 < C; c0 += 32) {
        #pragma unroll
        for (int i = ty; i < 32; i += 8) {
            Xs[i][tx] = Xn[(size_t)(c0 + i) * Pn + p0 + tx];
            Ws[i][tx] = Wt[(size_t)(o0 + i) * C + c0 + tx];
        }
        __syncthreads();
        #pragma unroll
        for (int kk = 0; kk < 32; kk++) {
            float wv = Ws[tx][kk];
            acc[0] += Xs[kk][ty]      * wv;
            acc[1] += Xs[kk][ty + 8]  * wv;
            acc[2] += Xs[kk][ty + 16] * wv;
            acc[3] += Xs[kk][ty + 24] * wv;
        }
        __syncthreads();
    }
    #pragma unroll
    for (int j = 0; j < 4; j++)
        outn[(size_t)(p0 + ty + 8 * j) * C + o0 + tx] = acc[j];
}

// ctx[n][o] = mean_p qt[n][p][o]
__global__ void context_kernel(const float* __restrict__ qt, float* __restrict__ ctx) {
    int o = blockIdx.x, n = blockIdx.y;
    const float* q = qt + (size_t)n * P * C + o;
    float s = 0.f;
    for (int p = threadIdx.x; p < P; p += 256) s += q[(size_t)p * C];
    __shared__ float red[256];
    red[threadIdx.x] = s;
    __syncthreads();
    for (int st = 128; st > 0; st >>= 1) {
        if (threadIdx.x < st) red[threadIdx.x] += red[threadIdx.x + st];
        __syncthreads();
    }
    if (threadIdx.x == 0) ctx[n * C + o] = red[0] * (1.0f / (float)P);
}

__global__ void mix_kernel(const float* __restrict__ ctx, const float* __restrict__ Wc,
                           const float* __restrict__ bc, float* __restrict__ mixw) {
    int n = blockIdx.x;
    __shared__ float lg[M];
    int m = threadIdx.x;
    if (m < M) {
        float s = bc[m];
        const float* cn = ctx + n * C;
        const float* wm = Wc + m * C;
        for (int o = 0; o < C; o++) s += cn[o] * wm[o];
        lg[m] = s;
    }
    __syncthreads();
    if (m == 0) {
        float mx = lg[0];
        #pragma unroll
        for (int i = 1; i < M; i++) mx = fmaxf(mx, lg[i]);
        float e[M], sum = 0.f;
        #pragma unroll
        for (int i = 0; i < M; i++) { e[i] = expf(lg[i] - mx); sum += e[i]; }
        #pragma unroll
        for (int i = 0; i < M; i++) mixw[n * M + i] = e[i] / sum;
    }
}

// Positional features. emb_x == emb_y element-wise, one kernel makes both.
// Output layout [m][i][d][j] (d-major so attn's pos-dot reads are coalesced).
__global__ void pos_kernel(const float* __restrict__ Wx, const float* __restrict__ Wy,
                           float* __restrict__ pfx, float* __restrict__ pfy) {
    __shared__ float emb[FEAT];
    int j = blockIdx.x;   // kv index (32)
    int i = blockIdx.y;   // q index  (64)
    int t = threadIdx.x;  // 288 = m*32 + d
    float diff = (float)i - 2.0f * (float)j;
    if (t < FEAT) {
        int l = (t < 72) ? t : (t - 72);
        float dm = powf(1000.0f, (4.0f / 288.0f) * (float)l);
        float wd = diff / dm;
        emb[t] = (t < 72) ? sinf(wd) : cosf(wd);
    }
    __syncthreads();
    float sx = 0.f, sy = 0.f;
    const float* wxr = Wx + t * FEAT;
    const float* wyr = Wy + t * FEAT;
    #pragma unroll 4
    for (int l = 0; l < FEAT; l++) {
        float e = emb[l];
        sx += e * wxr[l];
        sy += e * wyr[l];
    }
    const float inv_sqrt2 = 0.70710678118654752f;
    int m = t >> 5, dd = t & 31;
    int idx = ((m * 64 + i) * 32 + dd) * 32 + j;   // [m][i][d][j]
    pfx[idx] = sx * inv_sqrt2;
    pfy[idx] = sy * inv_sqrt2;
}

// ---------------- fused attention ----------------
// Per block: 16 queries (one row segment), all 9 heads, 512 threads.
// smem (floats): qT 288*16 | ks 512*33 (reused as V 32*288) | e 16*1024 |
//                acc 16*1025 | exs 16*32 | eys 16*32
#define QT 16
#define ATH 512
#define ACCS 1025
#define SM_QT   (288 * 16)
#define SM_KS   (512 * 33)
#define SM_E    (16 * 1024)
#define SM_ACC  (16 * ACCS)
#define SM_EXS  (16 * 32)
#define SMEM_FLOATS (SM_QT + SM_KS + SM_E + SM_ACC + 2 * SM_EXS)

__global__ __launch_bounds__(ATH, 1)
void attn_kernel(const float* __restrict__ qt, const float* __restrict__ kt,
                 const float* __restrict__ vt, const float* __restrict__ pfx,
                 const float* __restrict__ pfy, const float* __restrict__ mixw,
                 float* __restrict__ ao) {
    extern __shared__ float smp[];
    float* qT  = smp;                 // [o][16]
    float* ks  = qT + SM_QT;          // [sl][33]  (AV: V tile [32][288])
    float* e   = ks + SM_KS;          // [qi][1024]
    float* acc = e + SM_E;            // [qi][1025]
    float* exs = acc + SM_ACC;        // [qi][32]
    float* eys = exs + SM_EXS;        // [qi][32]

    int t = threadIdx.x;
    int n = blockIdx.y;
    int p0 = blockIdx.x * QT;
    const float* qn = qt + (size_t)n * P * C;
    const float* kn = kt + (size_t)n * S * C;
    const float* vn = vt + (size_t)n * S * C;
    int hq = p0 >> 6;
    int wq0 = p0 & 63;

    // load q transposed: qT[o][qi]  (coalesced global reads)
    for (int i = t; i < QT * 288; i += ATH) {
        int qi = i / 288, o = i - qi * 288;
        qT[o * 16 + qi] = qn[(size_t)p0 * C + i];
    }
    for (int i = t; i < QT * ACCS; i += ATH) acc[i] = 0.f;
    __syncthreads();

    int warp = t >> 5, lane = t & 31;
    int qg = t >> 7;          // 0..3  (q group of 4)
    int sg = t & 127;         // 0..127

    for (int m = 0; m < M; m++) {
        // ---- separable positional terms: exs[qi][v], eys[qi][u] ----
        {
            int qi = warp;    // warp per query
            const float* px = pfx + (((m * 64 + (wq0 + qi)) * 32) << 5);
            const float* py = pfy + (((m * 64 + hq) * 32) << 5);
            float sx = 0.f, sy = 0.f;
            #pragma unroll
            for (int dd = 0; dd < 32; dd++) {
                float qv = qT[(m * 32 + dd) * 16 + qi];          // broadcast
                sx += qv * px[(dd << 5) + lane];                 // coalesced
                sy += qv * py[(dd << 5) + lane];
            }
            exs[qi * 32 + lane] = sx;
            eys[qi * 32 + lane] = sy;
        }
        __syncthreads();

        // ---- QK energy: 4q x 4s register tile, s in chunks of 512 ----
        for (int s0 = 0; s0 < S; s0 += 512) {
            for (int i = t; i < 512 * 32; i += ATH) {
                int sl = i >> 5, dd = i & 31;
                ks[sl * 33 + dd] = kn[(size_t)(s0 + sl) * C + m * 32 + dd];
            }
            __syncthreads();
            float ar[4][4];
            float ex0 = exs[(qg * 4 + 0) * 32 + (sg & 31)];
            float ex1 = exs[(qg * 4 + 1) * 32 + (sg & 31)];
            float ex2 = exs[(qg * 4 + 2) * 32 + (sg & 31)];
            float ex3 = exs[(qg * 4 + 3) * 32 + (sg & 31)];
            #pragma unroll
            for (int c = 0; c < 4; c++) {
                int u = (s0 + sg + 128 * c) >> 5;
                ar[0][c] = ex0 + eys[(qg * 4 + 0) * 32 + u];
                ar[1][c] = ex1 + eys[(qg * 4 + 1) * 32 + u];
                ar[2][c] = ex2 + eys[(qg * 4 + 2) * 32 + u];
                ar[3][c] = ex3 + eys[(qg * 4 + 3) * 32 + u];
            }
            #pragma unroll
            for (int dd = 0; dd < 32; dd++) {
                float4 q4 = *(const float4*)&qT[(m * 32 + dd) * 16 + qg * 4];
                float kv0 = ks[(sg)        * 33 + dd];
                float kv1 = ks[(sg + 128)  * 33 + dd];
                float kv2 = ks[(sg + 256)  * 33 + dd];
                float kv3 = ks[(sg + 384)  * 33 + dd];
                ar[0][0] += q4.x * kv0; ar[0][1] += q4.x * kv1;
                ar[0][2] += q4.x * kv2; ar[0][3] += q4.x * kv3;
                ar[1][0] += q4.y * kv0; ar[1][1] += q4.y * kv1;
                ar[1][2] += q4.y * kv2; ar[1][3] += q4.y * kv3;
                ar[2][0] += q4.z * kv0; ar[2][1] += q4.z * kv1;
                ar[2][2] += q4.z * kv2; ar[2][3] += q4.z * kv3;
                ar[3][0] += q4.w * kv0; ar[3][1] += q4.w * kv1;
                ar[3][2] += q4.w * kv2; ar[3][3] += q4.w * kv3;
            }
            #pragma unroll
            for (int r = 0; r < 4; r++)
                #pragma unroll
                for (int c = 0; c < 4; c++)
                    e[(qg * 4 + r) * 1024 + s0 + sg + 128 * c] = ar[r][c];
            __syncthreads();
        }

        // ---- softmax (warp per query) + mix-weighted accumulate ----
        {
            int qi = warp;
            float wmix = mixw[n * M + m];
            float ev[32];
            float mx = -1e30f;
            #pragma unroll
            for (int j = 0; j < 32; j++) {
                ev[j] = e[qi * 1024 + lane + (j << 5)];
                mx = fmaxf(mx, ev[j]);
            }
            #pragma unroll
            for (int off = 16; off > 0; off >>= 1)
                mx = fmaxf(mx, __shfl_xor_sync(0xffffffffu, mx, off));
            float ssum = 0.f;
            #pragma unroll
            for (int j = 0; j < 32; j++) { ev[j] = __expf(ev[j] - mx); ssum += ev[j]; }
            #pragma unroll
            for (int off = 16; off > 0; off >>= 1)
                ssum += __shfl_xor_sync(0xffffffffu, ssum, off);
            float sc = wmix / ssum;
            #pragma unroll
            for (int j = 0; j < 32; j++)
                acc[qi * ACCS + lane + (j << 5)] += ev[j] * sc;
        }
        __syncthreads();
    }

    // ---- attn @ V ----
    // thread (qi = t&15, og = t>>4): outputs o = og + 32c, c<9.
    float* vs = ks;   // reuse: 32*288 = 9216 floats
    int qi_a = t & 15, og = t >> 4;
    float outr[9];
    #pragma unroll
    for (int c = 0; c < 9; c++) outr[c] = 0.f;
    for (int s0 = 0; s0 < S; s0 += 32) {
        for (int i = t; i < 32 * 288; i += ATH) {
            int sl = i / 288, o = i - sl * 288;
            vs[sl * 288 + o] = vn[(size_t)(s0 + sl) * C + o];
        }
        __syncthreads();
        float a_reg[32];
        #pragma unroll
        for (int ss = 0; ss < 32; ss++)
            a_reg[ss] = acc[qi_a * ACCS + s0 + ss];   // stride 1025: conflict-free
        #pragma unroll
        for (int ss = 0; ss < 32; ss++) {
            float a = a_reg[ss];
            const float* vp = vs + ss * 288 + og;
            #pragma unroll
            for (int c = 0; c < 9; c++)
                outr[c] += a * vp[c * 32];
        }
        __syncthreads();
    }
    float* aon = ao + (size_t)n * P * C + (size_t)(p0 + qi_a) * C + og;
    #pragma unroll
    for (int c = 0; c < 9; c++) aon[c * 32] = outr[c];
}

// out[n][c][p] = gamma*(sum_o A[n][p][o]*Wproj[c][o] + bproj[c]) + x[n][c][p]
__global__ void final_kernel(const float* __restrict__ A, const float* __restrict__ Wp,
                             const float* __restrict__ bp, const float* __restrict__ x,
                             const float* __restrict__ gamma, float* __restrict__ out) {
    __shared__ float As[32][33];
    __shared__ float Ws[32][33];
    int n = blockIdx.z;
    const float* An = A + (size_t)n * P * C;
    int p0 = blockIdx.x * 32, c0 = blockIdx.y * 32;
    int tx = threadIdx.x, ty = threadIdx.y;
    float acc[4] = {0.f, 0.f, 0.f, 0.f};
    for (int o0 = 0; o0 < C; o0 += 32) {
        #pragma unroll
        for (int i = ty; i < 32; i += 8) {
            As[i][tx] = An[(size_t)(p0 + i) * C + o0 + tx];
            Ws[i][tx] = Wp[(size_t)(c0 + i) * C + o0 + tx];
        }
        __syncthreads();
        #pragma unroll
        for (int kk = 0; kk < 32; kk++) {
            float av = As[tx][kk];
            acc[0] += av * Ws[ty][kk];
            acc[1] += av * Ws[ty + 8][kk];
            acc[2] += av * Ws[ty + 16][kk];
            acc[3] += av * Ws[ty + 24][kk];
        }
        __syncthreads();
    }
    float g = gamma[0];
    #pragma unroll
    for (int j = 0; j < 4; j++) {
        int c = c0 + ty + 8 * j;
        int p = p0 + tx;
        size_t oi = ((size_t)n * C + c) * P + p;
        out[oi] = g * (acc[j] + bp[c]) + x[oi];
    }
}

// ---------------- launch ----------------
extern "C" void kernel_launch(void* const* d_in, const int* in_sizes, int n_in,
                              void* d_out, int out_size) {
    const float* x     = (const float*)d_in[0];
    const float* Wq    = (const float*)d_in[1];
    const float* Wk    = (const float*)d_in[2];
    const float* Wv    = (const float*)d_in[3];
    const float* Wx    = (const float*)d_in[4];
    const float* Wy    = (const float*)d_in[5];
    const float* Wproj = (const float*)d_in[6];
    const float* bproj = (const float*)d_in[7];
    const float* Wc    = (const float*)d_in[8];
    const float* bc    = (const float*)d_in[9];
    const float* gamma = (const float*)d_in[10];
    float* out = (float*)d_out;

    float *xkv, *qt, *kt, *vt, *pfx, *pfy, *ctx, *mix, *ao;
    cudaGetSymbolAddress((void**)&xkv, g_xkv);
    cudaGetSymbolAddress((void**)&qt,  g_qt);
    cudaGetSymbolAddress((void**)&kt,  g_kt);
    cudaGetSymbolAddress((void**)&vt,  g_vt);
    cudaGetSymbolAddress((void**)&pfx, g_pfx);
    cudaGetSymbolAddress((void**)&pfy, g_pfy);
    cudaGetSymbolAddress((void**)&ctx, g_ctx);
    cudaGetSymbolAddress((void**)&mix, g_mix);
    cudaGetSymbolAddress((void**)&ao,  g_ao);

    size_t attn_smem = (size_t)SMEM_FLOATS * sizeof(float);
    cudaFuncSetAttribute(attn_kernel, cudaFuncAttributeMaxDynamicSharedMemorySize,
                         (int)attn_smem);

    xkv_kernel<<<(NB * C * S + 255) / 256, 256>>>(x, xkv);
    proj_kernel<<<dim3(P / 32, C / 32, NB), dim3(32, 8)>>>(x,   Wq, qt, P);
    proj_kernel<<<dim3(S / 32, C / 32, NB), dim3(32, 8)>>>(xkv, Wk, kt, S);
    proj_kernel<<<dim3(S / 32, C / 32, NB), dim3(32, 8)>>>(xkv, Wv, vt, S);
    context_kernel<<<dim3(C, NB), 256>>>(qt, ctx);
    mix_kernel<<<NB, 32>>>(ctx, Wc, bc, mix);
    pos_kernel<<<dim3(WKV, W), 288>>>(Wx, Wy, pfx, pfy);
    attn_kernel<<<dim3(P / QT, NB), ATH, attn_smem>>>(qt, kt, vt, pfx, pfy, mix, ao);
    final_kernel<<<dim3(P / 32, C / 32, NB), dim3(32, 8)>>>(ao, Wproj, bproj, x, gamma, out);
}

// round 3
// speedup vs baseline: 1.9744x; 1.2056x over previous
#include <cuda_runtime.h>
#include <cuda_bf16.h>
#include <math.h>

// Problem constants
#define NB   2
#define C    288
#define M    9
#define D    32
#define H    64
#define W    64
#define P    4096
#define HKV  32
#define WKV  32
#define S    1024
#define FEAT 144

// ---------------- device scratch ----------------
__device__ float g_wt [4 * C * C];         // transposed weights [c][o]: Wq,Wk,Wv,Wproj
__device__ float g_xkv[NB * C * S];        // [n][c][s]
__device__ float g_qt [NB * P * C];        // [n][p][o]
__device__ float g_kt [NB * S * C];        // [n][s][o]
__device__ float g_vt [NB * S * C];        // [n][s][o]
__device__ float g_pfx[M * W * D * WKV];   // [m][wq][d][v]
__device__ float g_pfy[M * H * D * HKV];   // [m][hq][d][u]
__device__ float g_ctx[NB * C];
__device__ float g_mix[NB * M];
__device__ float g_aot[NB * C * P];        // attn output TRANSPOSED [n][o][p]

// ---------------- weight transpose ----------------
__global__ void transpose_kernel(const float* __restrict__ Wq, const float* __restrict__ Wk,
                                 const float* __restrict__ Wv, const float* __restrict__ Wp,
                                 float* __restrict__ wt) {
    __shared__ float tile[32][33];
    const float* src = (blockIdx.z == 0) ? Wq : (blockIdx.z == 1) ? Wk
                     : (blockIdx.z == 2) ? Wv : Wp;
    float* dst = wt + (size_t)blockIdx.z * C * C;
    int r0 = blockIdx.y * 32, c0 = blockIdx.x * 32;
    int tx = threadIdx.x, ty = threadIdx.y;
    for (int i = ty; i < 32; i += 8) tile[i][tx] = src[(size_t)(r0 + i) * C + c0 + tx];
    __syncthreads();
    for (int i = ty; i < 32; i += 8) dst[(size_t)(c0 + i) * C + r0 + tx] = tile[tx][i];
}

// Strided gather: x_kv[n][c][s] = x[n][c][2u*64 + 2v]
__global__ void xkv_kernel(const float* __restrict__ x, float* __restrict__ xkv) {
    int idx = blockIdx.x * 256 + threadIdx.x;
    if (idx >= NB * C * S) return;
    int s = idx & (S - 1);
    int c = (idx >> 10) % C;
    int n = idx / (C * S);
    int u = s >> 5, v = s & 31;
    xkv[idx] = x[((size_t)n * C + c) * P + u * 128 + v * 2];
}

// out[n][p][o] = sum_c X[n][c][p] * WT[c][o].  tile 64p x 96o, 384 thr, 4x4 micro.
__global__ __launch_bounds__(384)
void proj_kernel(const float* __restrict__ X, const float* __restrict__ WT,
                 float* __restrict__ out, int Pn) {
    __shared__ float Xs[32 * 64];
    __shared__ float Ws[32 * 96];
    int n = blockIdx.z;
    const float* Xn = X + (size_t)n * C * Pn;
    float* outn = out + (size_t)n * Pn * C;
    int p0 = blockIdx.x * 64, o0 = blockIdx.y * 96;
    int t = threadIdx.x;
    int pi = t & 15, oj = t >> 4;
    float acc[4][4] = {};
    for (int c0 = 0; c0 < C; c0 += 32) {
        for (int i = t; i < 2048; i += 384)
            Xs[i] = Xn[(size_t)(c0 + (i >> 6)) * Pn + p0 + (i & 63)];
        for (int i = t; i < 3072; i += 384)
            Ws[i] = WT[(size_t)(c0 + i / 96) * C + o0 + i % 96];
        __syncthreads();
        #pragma unroll
        for (int kk = 0; kk < 32; kk++) {
            float4 xv = *(const float4*)&Xs[kk * 64 + pi * 4];
            float4 wv = *(const float4*)&Ws[kk * 96 + oj * 4];
            acc[0][0] += xv.x * wv.x; acc[0][1] += xv.x * wv.y;
            acc[0][2] += xv.x * wv.z; acc[0][3] += xv.x * wv.w;
            acc[1][0] += xv.y * wv.x; acc[1][1] += xv.y * wv.y;
            acc[1][2] += xv.y * wv.z; acc[1][3] += xv.y * wv.w;
            acc[2][0] += xv.z * wv.x; acc[2][1] += xv.z * wv.y;
            acc[2][2] += xv.z * wv.z; acc[2][3] += xv.z * wv.w;
            acc[3][0] += xv.w * wv.x; acc[3][1] += xv.w * wv.y;
            acc[3][2] += xv.w * wv.z; acc[3][3] += xv.w * wv.w;
        }
        __syncthreads();
    }
    #pragma unroll
    for (int r = 0; r < 4; r++) {
        float4 v = make_float4(acc[r][0], acc[r][1], acc[r][2], acc[r][3]);
        *(float4*)&outn[(size_t)(p0 + pi * 4 + r) * C + o0 + oj * 4] = v;
    }
}

// ctx[n][o] = mean_p qt[n][p][o]  (coalesced)
__global__ void context_kernel(const float* __restrict__ qt, float* __restrict__ ctx) {
    int o0 = blockIdx.x * 32, n = blockIdx.y;
    int lane = threadIdx.x & 31, w = threadIdx.x >> 5;
    const float* q = qt + (size_t)n * P * C + o0 + lane;
    float s = 0.f;
    for (int p = w; p < P; p += 8) s += q[(size_t)p * C];
    __shared__ float red[8][32];
    red[w][lane] = s;
    __syncthreads();
    if (w == 0) {
        float tot = 0.f;
        #pragma unroll
        for (int i = 0; i < 8; i++) tot += red[i][lane];
        ctx[n * C + o0 + lane] = tot * (1.0f / (float)P);
    }
}

__global__ void mix_kernel(const float* __restrict__ ctx, const float* __restrict__ Wc,
                           const float* __restrict__ bc, float* __restrict__ mixw) {
    int n = blockIdx.x;
    __shared__ float lg[M];
    int m = threadIdx.x;
    if (m < M) {
        float s = bc[m];
        const float* cn = ctx + n * C;
        const float* wm = Wc + m * C;
        for (int o = 0; o < C; o++) s += cn[o] * wm[o];
        lg[m] = s;
    }
    __syncthreads();
    if (m == 0) {
        float mx = lg[0];
        #pragma unroll
        for (int i = 1; i < M; i++) mx = fmaxf(mx, lg[i]);
        float e[M], sum = 0.f;
        #pragma unroll
        for (int i = 0; i < M; i++) { e[i] = expf(lg[i] - mx); sum += e[i]; }
        #pragma unroll
        for (int i = 0; i < M; i++) mixw[n * M + i] = e[i] / sum;
    }
}

// Positional features; emb_x == emb_y.  Output [m][i][d][j].
__global__ void pos_kernel(const float* __restrict__ Wx, const float* __restrict__ Wy,
                           float* __restrict__ pfx, float* __restrict__ pfy) {
    __shared__ float emb[FEAT];
    int j = blockIdx.x, i = blockIdx.y;
    int t = threadIdx.x;
    float diff = (float)i - 2.0f * (float)j;
    if (t < FEAT) {
        int l = (t < 72) ? t : (t - 72);
        float dm = powf(1000.0f, (4.0f / 288.0f) * (float)l);
        float wd = diff / dm;
        emb[t] = (t < 72) ? sinf(wd) : cosf(wd);
    }
    __syncthreads();
    float sx = 0.f, sy = 0.f;
    const float* wxr = Wx + t * FEAT;
    const float* wyr = Wy + t * FEAT;
    #pragma unroll 4
    for (int l = 0; l < FEAT; l++) {
        float e = emb[l];
        sx += e * wxr[l];
        sy += e * wyr[l];
    }
    const float inv_sqrt2 = 0.70710678118654752f;
    int m = t >> 5, dd = t & 31;
    int idx = ((m * 64 + i) * 32 + dd) * 32 + j;
    pfx[idx] = sx * inv_sqrt2;
    pfy[idx] = sy * inv_sqrt2;
}

// ---------------- fused attention: 1024 threads ----------------
#define QT 16
#define ATH 1024
#define ACCS 1025
#define SM_QT   (288 * 16)
#define SM_KS   (512 * 33)
#define SM_E    (16 * 1024)
#define SM_ACC  (16 * ACCS)
#define SM_EXS  (16 * 32)
#define SMEM_FLOATS (SM_QT + SM_KS + SM_E + SM_ACC + 2 * SM_EXS)

__global__ __launch_bounds__(ATH, 1)
void attn_kernel(const float* __restrict__ qt, const float* __restrict__ kt,
                 const float* __restrict__ vt, const float* __restrict__ pfx,
                 const float* __restrict__ pfy, const float* __restrict__ mixw,
                 float* __restrict__ aot) {
    extern __shared__ float smp[];
    float* qT  = smp;                 // [o][16]
    float* ks  = qT + SM_QT;          // [sl][33]; AV: vs[64][288] + red
    float* e   = ks + SM_KS;          // [qi][1024]
    float* acc = e + SM_E;            // [qi][1025]
    float* exs = acc + SM_ACC;        // [qi][32]
    float* eys = exs + SM_EXS;        // [qi][32]

    int t = threadIdx.x;
    int n = blockIdx.y;
    int p0 = blockIdx.x * QT;
    const float* qn = qt + (size_t)n * P * C;
    const float* kn = kt + (size_t)n * S * C;
    const float* vn = vt + (size_t)n * S * C;
    int hq = p0 >> 6;
    int wq0 = p0 & 63;

    for (int i = t; i < QT * 288; i += ATH) {
        int qi = i / 288, o = i - qi * 288;
        qT[o * 16 + qi] = qn[(size_t)p0 * C + i];
    }
    for (int i = t; i < QT * ACCS; i += ATH) acc[i] = 0.f;
    __syncthreads();

    int warp = t >> 5, lane = t & 31;
    int qg = t >> 8;          // 0..3 (QK q-group)
    int st = t & 255;         // 0..255 (QK s-thread)

    for (int m = 0; m < M; m++) {
        // ---- positional terms: warps 0-15 -> ex, warps 16-31 -> ey ----
        if (warp < 16) {
            int qi = warp;
            const float* px = pfx + (size_t)(m * 64 + wq0 + qi) * 1024;
            float sx = 0.f;
            #pragma unroll
            for (int dd = 0; dd < 32; dd++)
                sx += qT[(m * 32 + dd) * 16 + qi] * px[(dd << 5) + lane];
            exs[qi * 32 + lane] = sx;
        } else {
            int qi = warp - 16;
            const float* py = pfy + (size_t)(m * 64 + hq) * 1024;
            float sy = 0.f;
            #pragma unroll
            for (int dd = 0; dd < 32; dd++)
                sy += qT[(m * 32 + dd) * 16 + qi] * py[(dd << 5) + lane];
            eys[qi * 32 + lane] = sy;
        }
        __syncthreads();

        // ---- QK: 4q x 2s register tile, s chunks of 512 ----
        for (int s0 = 0; s0 < S; s0 += 512) {
            for (int i = t; i < 512 * 32; i += ATH) {
                int sl = i >> 5, dd = i & 31;
                ks[sl * 33 + dd] = kn[(size_t)(s0 + sl) * C + m * 32 + dd];
            }
            __syncthreads();
            float ar[4][2];
            #pragma unroll
            for (int r = 0; r < 4; r++) {
                float ex = exs[(qg * 4 + r) * 32 + (st & 31)];
                ar[r][0] = ex + eys[(qg * 4 + r) * 32 + ((s0 + st) >> 5)];
                ar[r][1] = ex + eys[(qg * 4 + r) * 32 + ((s0 + st + 256) >> 5)];
            }
            #pragma unroll
            for (int dd = 0; dd < 32; dd++) {
                float4 q4 = *(const float4*)&qT[(m * 32 + dd) * 16 + qg * 4];
                float kv0 = ks[st * 33 + dd];
                float kv1 = ks[(st + 256) * 33 + dd];
                ar[0][0] += q4.x * kv0; ar[0][1] += q4.x * kv1;
                ar[1][0] += q4.y * kv0; ar[1][1] += q4.y * kv1;
                ar[2][0] += q4.z * kv0; ar[2][1] += q4.z * kv1;
                ar[3][0] += q4.w * kv0; ar[3][1] += q4.w * kv1;
            }
            #pragma unroll
            for (int r = 0; r < 4; r++) {
                e[(qg * 4 + r) * 1024 + s0 + st]       = ar[r][0];
                e[(qg * 4 + r) * 1024 + s0 + st + 256] = ar[r][1];
            }
            __syncthreads();
        }

        // ---- softmax (warps 0-15, warp per query) + mix-weighted accumulate ----
        if (warp < 16) {
            int qi = warp;
            float wmix = mixw[n * M + m];
            float ev[32];
            float mx = -1e30f;
            #pragma unroll
            for (int j = 0; j < 32; j++) {
                ev[j] = e[qi * 1024 + lane + (j << 5)];
                mx = fmaxf(mx, ev[j]);
            }
            #pragma unroll
            for (int off = 16; off > 0; off >>= 1)
                mx = fmaxf(mx, __shfl_xor_sync(0xffffffffu, mx, off));
            float ssum = 0.f;
            #pragma unroll
            for (int j = 0; j < 32; j++) { ev[j] = __expf(ev[j] - mx); ssum += ev[j]; }
            #pragma unroll
            for (int off = 16; off > 0; off >>= 1)
                ssum += __shfl_xor_sync(0xffffffffu, ssum, off);
            float sc = wmix / ssum;
            #pragma unroll
            for (int j = 0; j < 32; j++)
                acc[qi * ACCS + lane + (j << 5)] += ev[j] * sc;
        }
        __syncthreads();
    }

    // ---- attn @ V ----
    // thread: qp = t&7 (2 queries), og = (t>>3)&31 (9 outputs o=og+32c), half = t>>8 (s quarter)
    float* vs  = ks;                  // [64][288]: rows = 4 quarters x 16
    float* red = ks + 64 * 288;       // 3 * 4608
    int qp = t & 7, og = (t >> 3) & 31, half = t >> 8;
    int qi0 = qp * 2;
    float outr[2][9];
    #pragma unroll
    for (int j = 0; j < 2; j++)
        #pragma unroll
        for (int c = 0; c < 9; c++) outr[j][c] = 0.f;

    for (int c0 = 0; c0 < 256; c0 += 16) {
        // tile rows: row = h*16 + r  -> s = h*256 + c0 + r
        for (int i = t; i < 64 * 288; i += ATH) {
            int row = i / 288, o = i - row * 288;
            int s = (row >> 4) * 256 + c0 + (row & 15);
            vs[row * 288 + o] = vn[(size_t)s * C + o];
        }
        __syncthreads();
        #pragma unroll
        for (int ss = 0; ss < 16; ss++) {
            float a0 = acc[qi0 * ACCS       + half * 256 + c0 + ss];
            float a1 = acc[(qi0 + 1) * ACCS + half * 256 + c0 + ss];
            const float* vp = vs + (half * 16 + ss) * 288 + og;
            #pragma unroll
            for (int c = 0; c < 9; c++) {
                float v = vp[c * 32];
                outr[0][c] += a0 * v;
                outr[1][c] += a1 * v;
            }
        }
        __syncthreads();
    }
    // combine 4 quarters
    if (half > 0) {
        float* rp = red + (half - 1) * 4608;
        #pragma unroll
        for (int j = 0; j < 2; j++)
            #pragma unroll
            for (int c = 0; c < 9; c++)
                rp[(qi0 + j) * 288 + og + 32 * c] = outr[j][c];
    }
    __syncthreads();
    if (half == 0) {
        float* an = aot + (size_t)n * C * P;
        #pragma unroll
        for (int j = 0; j < 2; j++)
            #pragma unroll
            for (int c = 0; c < 9; c++) {
                int ri = (qi0 + j) * 288 + og + 32 * c;
                float v = outr[j][c] + red[ri] + red[4608 + ri] + red[9216 + ri];
                an[(size_t)(og + 32 * c) * P + p0 + qi0 + j] = v;
            }
    }
}

// out[n][c][p] = gamma*(sum_o At[n][o][p]*WpT[o][c] + bp[c]) + x[n][c][p]
__global__ __launch_bounds__(384)
void final_kernel(const float* __restrict__ At, const float* __restrict__ WpT,
                  const float* __restrict__ bp, const float* __restrict__ x,
                  const float* __restrict__ gamma, float* __restrict__ out) {
    __shared__ float As[32 * 64];
    __shared__ float Ws[32 * 96];
    int n = blockIdx.z;
    const float* An = At + (size_t)n * C * P;
    int p0 = blockIdx.x * 64, c0 = blockIdx.y * 96;
    int t = threadIdx.x;
    int pi = t & 15, cj = t >> 4;
    float acc[4][4] = {};   // [c][p]
    for (int o0 = 0; o0 < C; o0 += 32) {
        for (int i = t; i < 2048; i += 384)
            As[i] = An[(size_t)(o0 + (i >> 6)) * P + p0 + (i & 63)];
        for (int i = t; i < 3072; i += 384)
            Ws[i] = WpT[(size_t)(o0 + i / 96) * C + c0 + i % 96];
        __syncthreads();
        #pragma unroll
        for (int kk = 0; kk < 32; kk++) {
            float4 av = *(const float4*)&As[kk * 64 + pi * 4];
            float4 wv = *(const float4*)&Ws[kk * 96 + cj * 4];
            acc[0][0] += wv.x * av.x; acc[0][1] += wv.x * av.y;
            acc[0][2] += wv.x * av.z; acc[0][3] += wv.x * av.w;
            acc[1][0] += wv.y * av.x; acc[1][1] += wv.y * av.y;
            acc[1][2] += wv.y * av.z; acc[1][3] += wv.y * av.w;
            acc[2][0] += wv.z * av.x; acc[2][1] += wv.z * av.y;
            acc[2][2] += wv.z * av.z; acc[2][3] += wv.z * av.w;
            acc[3][0] += wv.w * av.x; acc[3][1] += wv.w * av.y;
            acc[3][2] += wv.w * av.z; acc[3][3] += wv.w * av.w;
        }
        __syncthreads();
    }
    float g = gamma[0];
    #pragma unroll
    for (int r = 0; r < 4; r++) {
        int c = c0 + cj * 4 + r;
        size_t base = ((size_t)n * C + c) * P + p0 + pi * 4;
        float4 xr = *(const float4*)&x[base];
        float b = bp[c];
        float4 v;
        v.x = g * (acc[r][0] + b) + xr.x;
        v.y = g * (acc[r][1] + b) + xr.y;
        v.z = g * (acc[r][2] + b) + xr.z;
        v.w = g * (acc[r][3] + b) + xr.w;
        *(float4*)&out[base] = v;
    }
}

// ---------------- launch ----------------
extern "C" void kernel_launch(void* const* d_in, const int* in_sizes, int n_in,
                              void* d_out, int out_size) {
    const float* x     = (const float*)d_in[0];
    const float* Wq    = (const float*)d_in[1];
    const float* Wk    = (const float*)d_in[2];
    const float* Wv    = (const float*)d_in[3];
    const float* Wx    = (const float*)d_in[4];
    const float* Wy    = (const float*)d_in[5];
    const float* Wproj = (const float*)d_in[6];
    const float* bproj = (const float*)d_in[7];
    const float* Wc    = (const float*)d_in[8];
    const float* bc    = (const float*)d_in[9];
    const float* gamma = (const float*)d_in[10];
    float* out = (float*)d_out;

    float *wt, *xkv, *qt, *kt, *vt, *pfx, *pfy, *ctx, *mix, *aot;
    cudaGetSymbolAddress((void**)&wt,  g_wt);
    cudaGetSymbolAddress((void**)&xkv, g_xkv);
    cudaGetSymbolAddress((void**)&qt,  g_qt);
    cudaGetSymbolAddress((void**)&kt,  g_kt);
    cudaGetSymbolAddress((void**)&vt,  g_vt);
    cudaGetSymbolAddress((void**)&pfx, g_pfx);
    cudaGetSymbolAddress((void**)&pfy, g_pfy);
    cudaGetSymbolAddress((void**)&ctx, g_ctx);
    cudaGetSymbolAddress((void**)&mix, g_mix);
    cudaGetSymbolAddress((void**)&aot, g_aot);

    size_t attn_smem = (size_t)SMEM_FLOATS * sizeof(float);
    cudaFuncSetAttribute(attn_kernel, cudaFuncAttributeMaxDynamicSharedMemorySize,
                         (int)attn_smem);

    transpose_kernel<<<dim3(9, 9, 4), dim3(32, 8)>>>(Wq, Wk, Wv, Wproj, wt);
    xkv_kernel<<<(NB * C * S + 255) / 256, 256>>>(x, xkv);
    proj_kernel<<<dim3(P / 64, 3, NB), 384>>>(x,   wt + 0 * C * C, qt, P);
    proj_kernel<<<dim3(S / 64, 3, NB), 384>>>(xkv, wt + 1 * C * C, kt, S);
    proj_kernel<<<dim3(S / 64, 3, NB), 384>>>(xkv, wt + 2 * C * C, vt, S);
    context_kernel<<<dim3(C / 32, NB), 256>>>(qt, ctx);
    mix_kernel<<<NB, 32>>>(ctx, Wc, bc, mix);
    pos_kernel<<<dim3(WKV, W), 288>>>(Wx, Wy, pfx, pfy);
    attn_kernel<<<dim3(P / QT, NB), ATH, attn_smem>>>(qt, kt, vt, pfx, pfy, mix, aot);
    final_kernel<<<dim3(P / 64, 3, NB), 384>>>(aot, wt + 3 * C * C, bproj, x, gamma, out);
}

// round 4
// speedup vs baseline: 2.4124x; 1.2219x over previous
#include <cuda_runtime.h>
#include <cuda_bf16.h>
#include <math.h>
#include <stdint.h>

#define NB   2
#define C    288
#define M    9
#define D    32
#define H    64
#define W    64
#define P    4096
#define HKV  32
#define WKV  32
#define S    1024
#define FEAT 144

// ---------------- device scratch ----------------
__device__ float g_wt [4 * C * C];          // transposed weights
__device__ float g_xkv[NB * C * S];
__device__ float g_qt [NB * P * C];         // [n][p][o]
__device__ float g_kt [NB * S * C];         // [n][s][o]
__device__ float g_vt [NB * S * C];         // [n][s][o]
__device__ float g_pfx[M * W * D * WKV];    // [m][i][d][j]
__device__ float g_pfy[M * H * D * HKV];
__device__ float g_ctx[NB * C];
__device__ float g_mix[NB * M];
__device__ float g_ex [NB * M * P * 32];    // [n][m][p][v]
__device__ float g_ey [NB * M * P * 32];    // [n][m][p][u]
__device__ float g_energy[(size_t)NB * M * P * S];  // 302 MB
__device__ float g_attn[(size_t)NB * P * S];        // mixed attention
__device__ float g_aot[NB * C * P];         // attn output transposed [n][o][p]

// ---------------- tf32 helpers ----------------
__device__ __forceinline__ void split_tf32(float v, uint32_t& hi, uint32_t& lo) {
    asm("cvt.rna.tf32.f32 %0, %1;" : "=r"(hi) : "f"(v));
    float l = v - __uint_as_float(hi);
    asm("cvt.rna.tf32.f32 %0, %1;" : "=r"(lo) : "f"(l));
}
__device__ __forceinline__ void mma_tf32(float* c, const uint32_t* a, const uint32_t* b) {
    asm volatile(
        "mma.sync.aligned.m16n8k8.row.col.f32.tf32.tf32.f32 "
        "{%0,%1,%2,%3}, {%4,%5,%6,%7}, {%8,%9}, {%0,%1,%2,%3};"
        : "+f"(c[0]), "+f"(c[1]), "+f"(c[2]), "+f"(c[3])
        : "r"(a[0]), "r"(a[1]), "r"(a[2]), "r"(a[3]), "r"(b[0]), "r"(b[1]));
}

// ---------------- small kernels ----------------
__global__ void transpose_kernel(const float* __restrict__ Wq, const float* __restrict__ Wk,
                                 const float* __restrict__ Wv, const float* __restrict__ Wp,
                                 float* __restrict__ wt) {
    __shared__ float tile[32][33];
    const float* src = (blockIdx.z == 0) ? Wq : (blockIdx.z == 1) ? Wk
                     : (blockIdx.z == 2) ? Wv : Wp;
    float* dst = wt + (size_t)blockIdx.z * C * C;
    int r0 = blockIdx.y * 32, c0 = blockIdx.x * 32;
    int tx = threadIdx.x, ty = threadIdx.y;
    for (int i = ty; i < 32; i += 8) tile[i][tx] = src[(size_t)(r0 + i) * C + c0 + tx];
    __syncthreads();
    for (int i = ty; i < 32; i += 8) dst[(size_t)(c0 + i) * C + r0 + tx] = tile[tx][i];
}

__global__ void xkv_kernel(const float* __restrict__ x, float* __restrict__ xkv) {
    int idx = blockIdx.x * 256 + threadIdx.x;
    if (idx >= NB * C * S) return;
    int s = idx & (S - 1);
    int c = (idx >> 10) % C;
    int n = idx / (C * S);
    int u = s >> 5, v = s & 31;
    xkv[idx] = x[((size_t)n * C + c) * P + u * 128 + v * 2];
}

// out[n][p][o] = sum_c X[n][c][p] * WT[c][o]
__global__ __launch_bounds__(384)
void proj_kernel(const float* __restrict__ X, const float* __restrict__ WT,
                 float* __restrict__ out, int Pn) {
    __shared__ float Xs[32 * 64];
    __shared__ float Ws[32 * 96];
    int n = blockIdx.z;
    const float* Xn = X + (size_t)n * C * Pn;
    float* outn = out + (size_t)n * Pn * C;
    int p0 = blockIdx.x * 64, o0 = blockIdx.y * 96;
    int t = threadIdx.x;
    int pi = t & 15, oj = t >> 4;
    float acc[4][4] = {};
    for (int c0 = 0; c0 < C; c0 += 32) {
        for (int i = t; i < 2048; i += 384)
            Xs[i] = Xn[(size_t)(c0 + (i >> 6)) * Pn + p0 + (i & 63)];
        for (int i = t; i < 3072; i += 384)
            Ws[i] = WT[(size_t)(c0 + i / 96) * C + o0 + i % 96];
        __syncthreads();
        #pragma unroll
        for (int kk = 0; kk < 32; kk++) {
            float4 xv = *(const float4*)&Xs[kk * 64 + pi * 4];
            float4 wv = *(const float4*)&Ws[kk * 96 + oj * 4];
            acc[0][0] += xv.x * wv.x; acc[0][1] += xv.x * wv.y;
            acc[0][2] += xv.x * wv.z; acc[0][3] += xv.x * wv.w;
            acc[1][0] += xv.y * wv.x; acc[1][1] += xv.y * wv.y;
            acc[1][2] += xv.y * wv.z; acc[1][3] += xv.y * wv.w;
            acc[2][0] += xv.z * wv.x; acc[2][1] += xv.z * wv.y;
            acc[2][2] += xv.z * wv.z; acc[2][3] += xv.z * wv.w;
            acc[3][0] += xv.w * wv.x; acc[3][1] += xv.w * wv.y;
            acc[3][2] += xv.w * wv.z; acc[3][3] += xv.w * wv.w;
        }
        __syncthreads();
    }
    #pragma unroll
    for (int r = 0; r < 4; r++) {
        float4 v = make_float4(acc[r][0], acc[r][1], acc[r][2], acc[r][3]);
        *(float4*)&outn[(size_t)(p0 + pi * 4 + r) * C + o0 + oj * 4] = v;
    }
}

__global__ void context_kernel(const float* __restrict__ qt, float* __restrict__ ctx) {
    int o0 = blockIdx.x * 32, n = blockIdx.y;
    int lane = threadIdx.x & 31, w = threadIdx.x >> 5;
    const float* q = qt + (size_t)n * P * C + o0 + lane;
    float s = 0.f;
    for (int p = w; p < P; p += 8) s += q[(size_t)p * C];
    __shared__ float red[8][32];
    red[w][lane] = s;
    __syncthreads();
    if (w == 0) {
        float tot = 0.f;
        #pragma unroll
        for (int i = 0; i < 8; i++) tot += red[i][lane];
        ctx[n * C + o0 + lane] = tot * (1.0f / (float)P);
    }
}

__global__ void mix_kernel(const float* __restrict__ ctx, const float* __restrict__ Wc,
                           const float* __restrict__ bc, float* __restrict__ mixw) {
    int n = blockIdx.x;
    __shared__ float lg[M];
    int m = threadIdx.x;
    if (m < M) {
        float s = bc[m];
        const float* cn = ctx + n * C;
        const float* wm = Wc + m * C;
        for (int o = 0; o < C; o++) s += cn[o] * wm[o];
        lg[m] = s;
    }
    __syncthreads();
    if (m == 0) {
        float mx = lg[0];
        #pragma unroll
        for (int i = 1; i < M; i++) mx = fmaxf(mx, lg[i]);
        float e[M], sum = 0.f;
        #pragma unroll
        for (int i = 0; i < M; i++) { e[i] = expf(lg[i] - mx); sum += e[i]; }
        #pragma unroll
        for (int i = 0; i < M; i++) mixw[n * M + i] = e[i] / sum;
    }
}

__global__ void pos_kernel(const float* __restrict__ Wx, const float* __restrict__ Wy,
                           float* __restrict__ pfx, float* __restrict__ pfy) {
    __shared__ float emb[FEAT];
    int j = blockIdx.x, i = blockIdx.y;
    int t = threadIdx.x;
    float diff = (float)i - 2.0f * (float)j;
    if (t < FEAT) {
        int l = (t < 72) ? t : (t - 72);
        float dm = powf(1000.0f, (4.0f / 288.0f) * (float)l);
        float wd = diff / dm;
        emb[t] = (t < 72) ? sinf(wd) : cosf(wd);
    }
    __syncthreads();
    float sx = 0.f, sy = 0.f;
    const float* wxr = Wx + t * FEAT;
    const float* wyr = Wy + t * FEAT;
    #pragma unroll 4
    for (int l = 0; l < FEAT; l++) {
        float e = emb[l];
        sx += e * wxr[l];
        sy += e * wyr[l];
    }
    const float inv_sqrt2 = 0.70710678118654752f;
    int m = t >> 5, dd = t & 31;
    int idx = ((m * 64 + i) * 32 + dd) * 32 + j;
    pfx[idx] = sx * inv_sqrt2;
    pfy[idx] = sy * inv_sqrt2;
}

// EX[n][m][p=(h,w)][v] = sum_d q[n][p][m*32+d] * pfx[m][w][d][v].  grid (W, M, NB)
__global__ __launch_bounds__(256)
void ex_kernel(const float* __restrict__ qt, const float* __restrict__ pfx,
               float* __restrict__ ex) {
    __shared__ float qs[64 * 33];
    __shared__ float pfs[32 * 33];
    int w = blockIdx.x, m = blockIdx.y, n = blockIdx.z;
    int t = threadIdx.x;
    for (int i = t; i < 1024; i += 256)
        pfs[(i >> 5) * 33 + (i & 31)] = pfx[(m * 64 + w) * 1024 + i];
    for (int i = t; i < 2048; i += 256) {
        int hh = i >> 5, dd = i & 31;
        qs[hh * 33 + dd] = qt[((size_t)n * P + hh * 64 + w) * C + m * 32 + dd];
    }
    __syncthreads();
    int v = t & 31, h0 = t >> 5;
    #pragma unroll
    for (int r = 0; r < 8; r++) {
        int h = h0 + 8 * r;
        float a = 0.f;
        #pragma unroll
        for (int dd = 0; dd < 32; dd++)
            a += qs[h * 33 + dd] * pfs[dd * 33 + v];
        ex[((size_t)(n * M + m) * P + h * 64 + w) * 32 + v] = a;
    }
}

// EY[n][m][p=(h,w)][u] = sum_d q[n][p][m*32+d] * pfy[m][h][d][u].  grid (H, M, NB)
__global__ __launch_bounds__(256)
void ey_kernel(const float* __restrict__ qt, const float* __restrict__ pfy,
               float* __restrict__ ey) {
    __shared__ float qs[64 * 33];
    __shared__ float pfs[32 * 33];
    int h = blockIdx.x, m = blockIdx.y, n = blockIdx.z;
    int t = threadIdx.x;
    for (int i = t; i < 1024; i += 256)
        pfs[(i >> 5) * 33 + (i & 31)] = pfy[(m * 64 + h) * 1024 + i];
    for (int i = t; i < 2048; i += 256) {
        int ww = i >> 5, dd = i & 31;
        qs[ww * 33 + dd] = qt[((size_t)n * P + h * 64 + ww) * C + m * 32 + dd];
    }
    __syncthreads();
    int u = t & 31, w0 = t >> 5;
    #pragma unroll
    for (int r = 0; r < 8; r++) {
        int ww = w0 + 8 * r;
        float a = 0.f;
        #pragma unroll
        for (int dd = 0; dd < 32; dd++)
            a += qs[ww * 33 + dd] * pfs[dd * 33 + u];
        ey[((size_t)(n * M + m) * P + h * 64 + ww) * 32 + u] = a;
    }
}

// ---------------- energy GEMM (tf32x3 mma) ----------------
// e[n][m][p][s] = q_m[p,:32] . k_m[s,:32] + EX[p][s&31] + EY[p][s>>5]
// grid (S/128, P/128, NB*M), block 256 (8 warps, warp tile 32p x 64s)
__global__ __launch_bounds__(256)
void energy_kernel(const float* __restrict__ qt, const float* __restrict__ kt,
                   const float* __restrict__ ex, const float* __restrict__ ey,
                   float* __restrict__ eout) {
    extern __shared__ float dyn[];
    float* As_hi = dyn;            // [128p][36]
    float* As_lo = dyn + 4608;
    float* Bs_hi = dyn + 9216;     // [128s][36]
    float* Bs_lo = dyn + 13824;
    float* EXs   = dyn + 18432;    // [128p][32]
    float* EYs   = dyn + 22528;    // [128p][32]

    int s0 = blockIdx.x * 128, p0 = blockIdx.y * 128;
    int n = blockIdx.z / M, m = blockIdx.z % M;
    int t = threadIdx.x;
    int warp = t >> 5, lane = t & 31;
    int g = lane >> 2, tg = lane & 3;
    int wp = warp >> 1, ws = warp & 1;     // 4 p-warps x 2 s-warps

    const float* qn = qt + (size_t)n * P * C + (size_t)m * 32;
    const float* kn = kt + (size_t)n * S * C + (size_t)m * 32;
    size_t exbase = ((size_t)(n * M + m) * P + p0) * 32;

    for (int i = t; i < 4096; i += 256) {
        int pl = i >> 5, kk = i & 31;
        uint32_t hi, lo;
        split_tf32(qn[(size_t)(p0 + pl) * C + kk], hi, lo);
        As_hi[pl * 36 + kk] = __uint_as_float(hi);
        As_lo[pl * 36 + kk] = __uint_as_float(lo);
        split_tf32(kn[(size_t)(s0 + pl) * C + kk], hi, lo);
        Bs_hi[pl * 36 + kk] = __uint_as_float(hi);
        Bs_lo[pl * 36 + kk] = __uint_as_float(lo);
        EXs[i] = ex[exbase + i];
        EYs[i] = ey[exbase + i];
    }
    __syncthreads();

    float acc[2][8][4];
    #pragma unroll
    for (int a = 0; a < 2; a++)
        #pragma unroll
        for (int b = 0; b < 8; b++)
            #pragma unroll
            for (int c = 0; c < 4; c++) acc[a][b][c] = 0.f;

    #pragma unroll
    for (int ks = 0; ks < 4; ks++) {
        uint32_t ah[2][4], al[2][4];
        #pragma unroll
        for (int mt = 0; mt < 2; mt++) {
            int pb = wp * 32 + mt * 16;
            ah[mt][0] = __float_as_uint(As_hi[(pb + g) * 36 + ks * 8 + tg]);
            ah[mt][1] = __float_as_uint(As_hi[(pb + g + 8) * 36 + ks * 8 + tg]);
            ah[mt][2] = __float_as_uint(As_hi[(pb + g) * 36 + ks * 8 + tg + 4]);
            ah[mt][3] = __float_as_uint(As_hi[(pb + g + 8) * 36 + ks * 8 + tg + 4]);
            al[mt][0] = __float_as_uint(As_lo[(pb + g) * 36 + ks * 8 + tg]);
            al[mt][1] = __float_as_uint(As_lo[(pb + g + 8) * 36 + ks * 8 + tg]);
            al[mt][2] = __float_as_uint(As_lo[(pb + g) * 36 + ks * 8 + tg + 4]);
            al[mt][3] = __float_as_uint(As_lo[(pb + g + 8) * 36 + ks * 8 + tg + 4]);
        }
        #pragma unroll
        for (int nf = 0; nf < 8; nf++) {
            int sb = ws * 64 + nf * 8;
            uint32_t bh[2], bl[2];
            bh[0] = __float_as_uint(Bs_hi[(sb + g) * 36 + ks * 8 + tg]);
            bh[1] = __float_as_uint(Bs_hi[(sb + g) * 36 + ks * 8 + tg + 4]);
            bl[0] = __float_as_uint(Bs_lo[(sb + g) * 36 + ks * 8 + tg]);
            bl[1] = __float_as_uint(Bs_lo[(sb + g) * 36 + ks * 8 + tg + 4]);
            #pragma unroll
            for (int mt = 0; mt < 2; mt++) {
                mma_tf32(acc[mt][nf], ah[mt], bh);
                mma_tf32(acc[mt][nf], ah[mt], bl);
                mma_tf32(acc[mt][nf], al[mt], bh);
            }
        }
    }

    // epilogue: add EX/EY, store float2 pairs
    float* ebase = eout + ((size_t)(n * M + m) * P + p0) * S + s0;
    #pragma unroll
    for (int mt = 0; mt < 2; mt++) {
        #pragma unroll
        for (int nf = 0; nf < 8; nf++) {
            int sl = ws * 64 + nf * 8 + tg * 2;
            int u = (s0 + sl) >> 5;
            int v0 = sl & 31, v1 = (sl + 1) & 31;
            #pragma unroll
            for (int half = 0; half < 2; half++) {
                int pl = wp * 32 + mt * 16 + g + half * 8;
                float2 r;
                r.x = acc[mt][nf][half * 2]     + EXs[pl * 32 + v0] + EYs[pl * 32 + u];
                r.y = acc[mt][nf][half * 2 + 1] + EXs[pl * 32 + v1] + EYs[pl * 32 + u];
                *(float2*)&ebase[(size_t)pl * S + sl] = r;
            }
        }
    }
}

// ---------------- softmax + head mix ----------------
// attn[n][p][s] = sum_m mixw[n][m] * softmax_s(e[n][m][p][:])
__global__ __launch_bounds__(256)
void softmax_kernel(const float* __restrict__ e, const float* __restrict__ mixw,
                    float* __restrict__ attn) {
    int p = blockIdx.x, n = blockIdx.y;
    int t = threadIdx.x, lane = t & 31, warp = t >> 5;
    __shared__ float red[8];
    __shared__ float bval;
    float acc[4] = {0.f, 0.f, 0.f, 0.f};
    for (int m = 0; m < M; m++) {
        const float* ep = e + ((size_t)(n * M + m) * P + p) * S;
        float ev[4];
        #pragma unroll
        for (int j = 0; j < 4; j++) ev[j] = ep[t + 256 * j];
        float mx = fmaxf(fmaxf(ev[0], ev[1]), fmaxf(ev[2], ev[3]));
        #pragma unroll
        for (int off = 16; off > 0; off >>= 1)
            mx = fmaxf(mx, __shfl_xor_sync(0xffffffffu, mx, off));
        if (lane == 0) red[warp] = mx;
        __syncthreads();
        if (t == 0) {
            float v = red[0];
            #pragma unroll
            for (int i = 1; i < 8; i++) v = fmaxf(v, red[i]);
            bval = v;
        }
        __syncthreads();
        mx = bval;
        float ssum = 0.f;
        #pragma unroll
        for (int j = 0; j < 4; j++) { ev[j] = __expf(ev[j] - mx); ssum += ev[j]; }
        #pragma unroll
        for (int off = 16; off > 0; off >>= 1)
            ssum += __shfl_xor_sync(0xffffffffu, ssum, off);
        __syncthreads();   // protect red reuse
        if (lane == 0) red[warp] = ssum;
        __syncthreads();
        if (t == 0) {
            float v = 0.f;
            #pragma unroll
            for (int i = 0; i < 8; i++) v += red[i];
            bval = v;
        }
        __syncthreads();
        float sc = mixw[n * M + m] / bval;
        #pragma unroll
        for (int j = 0; j < 4; j++) acc[j] += ev[j] * sc;
        __syncthreads();   // protect bval before next head
    }
    float* ap = attn + ((size_t)n * P + p) * S;
    #pragma unroll
    for (int j = 0; j < 4; j++) ap[t + 256 * j] = acc[j];
}

// ---------------- AV GEMM (tf32x3 mma) ----------------
// aoT[n][o][p] = sum_s attn[n][p][s] * vt[n][s][o]
// grid (288/96, P/64, NB), block 256 (8 warps: 2p x 4o, warp tile 32p x 24o)
__global__ __launch_bounds__(256)
void av_kernel(const float* __restrict__ attn, const float* __restrict__ vt,
               float* __restrict__ aot) {
    __shared__ float sm[11008];
    float* As_hi = sm;          // [64p][36]
    float* As_lo = sm + 2304;
    float* Bs_hi = sm + 4608;   // [32k][100]
    float* Bs_lo = sm + 7808;

    int o0 = blockIdx.x * 96, p0 = blockIdx.y * 64, n = blockIdx.z;
    int t = threadIdx.x;
    int warp = t >> 5, lane = t & 31;
    int g = lane >> 2, tg = lane & 3;
    int wp = warp & 1, wo = warp >> 1;

    const float* an = attn + (size_t)n * P * S;
    const float* vn = vt + (size_t)n * S * C;

    float acc[2][3][4];
    #pragma unroll
    for (int a = 0; a < 2; a++)
        #pragma unroll
        for (int b = 0; b < 3; b++)
            #pragma unroll
            for (int c = 0; c < 4; c++) acc[a][b][c] = 0.f;

    for (int k0 = 0; k0 < S; k0 += 32) {
        for (int i = t; i < 2048; i += 256) {
            int pl = i >> 5, kk = i & 31;
            uint32_t hi, lo;
            split_tf32(an[(size_t)(p0 + pl) * S + k0 + kk], hi, lo);
            As_hi[pl * 36 + kk] = __uint_as_float(hi);
            As_lo[pl * 36 + kk] = __uint_as_float(lo);
        }
        for (int i = t; i < 3072; i += 256) {
            int kk = i / 96, ol = i - kk * 96;
            uint32_t hi, lo;
            split_tf32(vn[(size_t)(k0 + kk) * C + o0 + ol], hi, lo);
            Bs_hi[kk * 100 + ol] = __uint_as_float(hi);
            Bs_lo[kk * 100 + ol] = __uint_as_float(lo);
        }
        __syncthreads();
        #pragma unroll
        for (int ks = 0; ks < 4; ks++) {
            uint32_t ah[2][4], al[2][4];
            #pragma unroll
            for (int mt = 0; mt < 2; mt++) {
                int pb = wp * 32 + mt * 16;
                ah[mt][0] = __float_as_uint(As_hi[(pb + g) * 36 + ks * 8 + tg]);
                ah[mt][1] = __float_as_uint(As_hi[(pb + g + 8) * 36 + ks * 8 + tg]);
                ah[mt][2] = __float_as_uint(As_hi[(pb + g) * 36 + ks * 8 + tg + 4]);
                ah[mt][3] = __float_as_uint(As_hi[(pb + g + 8) * 36 + ks * 8 + tg + 4]);
                al[mt][0] = __float_as_uint(As_lo[(pb + g) * 36 + ks * 8 + tg]);
                al[mt][1] = __float_as_uint(As_lo[(pb + g + 8) * 36 + ks * 8 + tg]);
                al[mt][2] = __float_as_uint(As_lo[(pb + g) * 36 + ks * 8 + tg + 4]);
                al[mt][3] = __float_as_uint(As_lo[(pb + g + 8) * 36 + ks * 8 + tg + 4]);
            }
            #pragma unroll
            for (int nf = 0; nf < 3; nf++) {
                int ob = wo * 24 + nf * 8;
                uint32_t bh[2], bl[2];
                bh[0] = __float_as_uint(Bs_hi[(ks * 8 + tg) * 100 + ob + g]);
                bh[1] = __float_as_uint(Bs_hi[(ks * 8 + tg + 4) * 100 + ob + g]);
                bl[0] = __float_as_uint(Bs_lo[(ks * 8 + tg) * 100 + ob + g]);
                bl[1] = __float_as_uint(Bs_lo[(ks * 8 + tg + 4) * 100 + ob + g]);
                #pragma unroll
                for (int mt = 0; mt < 2; mt++) {
                    mma_tf32(acc[mt][nf], ah[mt], bh);
                    mma_tf32(acc[mt][nf], ah[mt], bl);
                    mma_tf32(acc[mt][nf], al[mt], bh);
                }
            }
        }
        __syncthreads();
    }

    // stage transposed [o][p] then coalesced store
    float* stage = sm;   // needs 96*68 = 6528 floats
    #pragma unroll
    for (int mt = 0; mt < 2; mt++)
        #pragma unroll
        for (int nf = 0; nf < 3; nf++)
            #pragma unroll
            for (int c = 0; c < 4; c++) {
                int oo = wo * 24 + nf * 8 + tg * 2 + (c & 1);
                int pp = wp * 32 + mt * 16 + g + ((c >> 1) * 8);
                stage[oo * 68 + pp] = acc[mt][nf][c];
            }
    __syncthreads();
    float* ab = aot + ((size_t)n * C + o0) * P + p0;
    for (int i = t; i < 96 * 64; i += 256) {
        int orr = i >> 6, pc = i & 63;
        ab[(size_t)orr * P + pc] = stage[orr * 68 + pc];
    }
}

// out[n][c][p] = gamma*(sum_o At[n][o][p]*WpT[o][c] + bp[c]) + x[n][c][p]
__global__ __launch_bounds__(384)
void final_kernel(const float* __restrict__ At, const float* __restrict__ WpT,
                  const float* __restrict__ bp, const float* __restrict__ x,
                  const float* __restrict__ gamma, float* __restrict__ out) {
    __shared__ float As[32 * 64];
    __shared__ float Ws[32 * 96];
    int n = blockIdx.z;
    const float* An = At + (size_t)n * C * P;
    int p0 = blockIdx.x * 64, c0 = blockIdx.y * 96;
    int t = threadIdx.x;
    int pi = t & 15, cj = t >> 4;
    float acc[4][4] = {};
    for (int o0 = 0; o0 < C; o0 += 32) {
        for (int i = t; i < 2048; i += 384)
            As[i] = An[(size_t)(o0 + (i >> 6)) * P + p0 + (i & 63)];
        for (int i = t; i < 3072; i += 384)
            Ws[i] = WpT[(size_t)(o0 + i / 96) * C + c0 + i % 96];
        __syncthreads();
        #pragma unroll
        for (int kk = 0; kk < 32; kk++) {
            float4 av = *(const float4*)&As[kk * 64 + pi * 4];
            float4 wv = *(const float4*)&Ws[kk * 96 + cj * 4];
            acc[0][0] += wv.x * av.x; acc[0][1] += wv.x * av.y;
            acc[0][2] += wv.x * av.z; acc[0][3] += wv.x * av.w;
            acc[1][0] += wv.y * av.x; acc[1][1] += wv.y * av.y;
            acc[1][2] += wv.y * av.z; acc[1][3] += wv.y * av.w;
            acc[2][0] += wv.z * av.x; acc[2][1] += wv.z * av.y;
            acc[2][2] += wv.z * av.z; acc[2][3] += wv.z * av.w;
            acc[3][0] += wv.w * av.x; acc[3][1] += wv.w * av.y;
            acc[3][2] += wv.w * av.z; acc[3][3] += wv.w * av.w;
        }
        __syncthreads();
    }
    float g = gamma[0];
    #pragma unroll
    for (int r = 0; r < 4; r++) {
        int c = c0 + cj * 4 + r;
        size_t base = ((size_t)n * C + c) * P + p0 + pi * 4;
        float4 xr = *(const float4*)&x[base];
        float b = bp[c];
        float4 v;
        v.x = g * (acc[r][0] + b) + xr.x;
        v.y = g * (acc[r][1] + b) + xr.y;
        v.z = g * (acc[r][2] + b) + xr.z;
        v.w = g * (acc[r][3] + b) + xr.w;
        *(float4*)&out[base] = v;
    }
}

// ---------------- launch ----------------
extern "C" void kernel_launch(void* const* d_in, const int* in_sizes, int n_in,
                              void* d_out, int out_size) {
    const float* x     = (const float*)d_in[0];
    const float* Wq    = (const float*)d_in[1];
    const float* Wk    = (const float*)d_in[2];
    const float* Wv    = (const float*)d_in[3];
    const float* Wx    = (const float*)d_in[4];
    const float* Wy    = (const float*)d_in[5];
    const float* Wproj = (const float*)d_in[6];
    const float* bproj = (const float*)d_in[7];
    const float* Wc    = (const float*)d_in[8];
    const float* bc    = (const float*)d_in[9];
    const float* gamma = (const float*)d_in[10];
    float* out = (float*)d_out;

    float *wt, *xkv, *qt, *kt, *vt, *pfx, *pfy, *ctx, *mix, *exb, *eyb, *en, *attn, *aot;
    cudaGetSymbolAddress((void**)&wt,  g_wt);
    cudaGetSymbolAddress((void**)&xkv, g_xkv);
    cudaGetSymbolAddress((void**)&qt,  g_qt);
    cudaGetSymbolAddress((void**)&kt,  g_kt);
    cudaGetSymbolAddress((void**)&vt,  g_vt);
    cudaGetSymbolAddress((void**)&pfx, g_pfx);
    cudaGetSymbolAddress((void**)&pfy, g_pfy);
    cudaGetSymbolAddress((void**)&ctx, g_ctx);
    cudaGetSymbolAddress((void**)&mix, g_mix);
    cudaGetSymbolAddress((void**)&exb, g_ex);
    cudaGetSymbolAddress((void**)&eyb, g_ey);
    cudaGetSymbolAddress((void**)&en,  g_energy);
    cudaGetSymbolAddress((void**)&attn, g_attn);
    cudaGetSymbolAddress((void**)&aot, g_aot);

    static int smem_set = 0;
    size_t energy_smem = 26624 * sizeof(float);
    cudaFuncSetAttribute(energy_kernel, cudaFuncAttributeMaxDynamicSharedMemorySize,
                         (int)energy_smem);

    transpose_kernel<<<dim3(9, 9, 4), dim3(32, 8)>>>(Wq, Wk, Wv, Wproj, wt);
    xkv_kernel<<<(NB * C * S + 255) / 256, 256>>>(x, xkv);
    proj_kernel<<<dim3(P / 64, 3, NB), 384>>>(x,   wt + 0 * C * C, qt, P);
    proj_kernel<<<dim3(S / 64, 3, NB), 384>>>(xkv, wt + 1 * C * C, kt, S);
    proj_kernel<<<dim3(S / 64, 3, NB), 384>>>(xkv, wt + 2 * C * C, vt, S);
    context_kernel<<<dim3(C / 32, NB), 256>>>(qt, ctx);
    mix_kernel<<<NB, 32>>>(ctx, Wc, bc, mix);
    pos_kernel<<<dim3(WKV, W), 288>>>(Wx, Wy, pfx, pfy);
    ex_kernel<<<dim3(W, M, NB), 256>>>(qt, pfx, exb);
    ey_kernel<<<dim3(H, M, NB), 256>>>(qt, pfy, eyb);
    energy_kernel<<<dim3(S / 128, P / 128, NB * M), 256, energy_smem>>>(qt, kt, exb, eyb, en);
    softmax_kernel<<<dim3(P, NB), 256>>>(en, mix, attn);
    av_kernel<<<dim3(3, P / 64, NB), 256>>>(attn, vt, aot);
    final_kernel<<<dim3(P / 64, 3, NB), 384>>>(aot, wt + 3 * C * C, bproj, x, gamma, out);
}